// round 5
// baseline (speedup 1.0000x reference)
#include <cuda_runtime.h>
#include <math.h>

#define B_  2
#define L_  2048
#define C_  1024
#define H_  16
#define HD_ 64
#define M_  (B_*L_)      // 4096
#define NQKV_ (3*C_)     // 3072

// Scratch (allocation-free rule: device globals)
__device__ float g_q [B_*H_*L_*HD_];   // [B,H,L,HD]
__device__ float g_k [B_*H_*L_*HD_];
__device__ float g_v [B_*H_*L_*HD_];
__device__ float g_ao[B_*L_*C_];       // attention output [B,L,C]

// ---------------------------------------------------------------------------
// GEMM: out[m,n] = sum_k A[m,k] * W[n,k]   (A:[M,1024] row-major, W:[N,1024] row-major)
// BM=BN=128, BK=8, 256 threads, 8x8 per-thread tile, double-buffered smem.
// MODE 0: qkv epilogue (scatter to g_q/g_k/g_v with q_bias / 0 / v_bias)
// MODE 1: proj epilogue (A is g_ao, add b_proj, write d_out)
// ---------------------------------------------------------------------------
template<int MODE>
__global__ __launch_bounds__(256) void gemm_kernel(
    const float* __restrict__ Ain,
    const float* __restrict__ W,
    const float* __restrict__ bias0,   // q_bias (mode0) / b_proj (mode1)
    const float* __restrict__ bias1,   // v_bias (mode0) / unused
    float* __restrict__ out)           // unused (mode0) / d_out (mode1)
{
    __shared__ float As[2][8][132];
    __shared__ float Ws[2][8][132];

    const int K = 1024;
    const int NKT = K / 8;             // 128 k-tiles

    const float* A = (MODE == 1) ? (const float*)g_ao : Ain;

    const int tid = threadIdx.x;
    const int tx  = tid & 15;
    const int ty  = tid >> 4;
    const int m0  = blockIdx.y * 128;
    const int n0  = blockIdx.x * 128;

    const int lrow = tid >> 1;         // 0..127
    const int lkg  = (tid & 1) * 4;    // 0 or 4

    const float* Ap = A + (size_t)(m0 + lrow) * K + lkg;
    const float* Wp = W + (size_t)(n0 + lrow) * K + lkg;

    float acc[8][8];
    #pragma unroll
    for (int i = 0; i < 8; i++)
        #pragma unroll
        for (int j = 0; j < 8; j++) acc[i][j] = 0.f;

    float (*cA)[132] = As[0];
    float (*cW)[132] = Ws[0];
    float (*nA)[132] = As[1];
    float (*nW)[132] = Ws[1];

    // preload tile 0
    {
        float4 av = *(const float4*)(Ap);
        float4 wv = *(const float4*)(Wp);
        cA[lkg+0][lrow] = av.x; cA[lkg+1][lrow] = av.y;
        cA[lkg+2][lrow] = av.z; cA[lkg+3][lrow] = av.w;
        cW[lkg+0][lrow] = wv.x; cW[lkg+1][lrow] = wv.y;
        cW[lkg+2][lrow] = wv.z; cW[lkg+3][lrow] = wv.w;
    }
    __syncthreads();

    for (int kt = 0; kt < NKT; kt++) {
        float4 av, wv;
        const bool has_next = (kt + 1 < NKT);
        if (has_next) {
            av = *(const float4*)(Ap + (kt + 1) * 8);
            wv = *(const float4*)(Wp + (kt + 1) * 8);
        }

        #pragma unroll
        for (int kk = 0; kk < 8; kk++) {
            float fa[8], fb[8];
            *(float4*)&fa[0] = *(float4*)&cA[kk][ty*8];
            *(float4*)&fa[4] = *(float4*)&cA[kk][ty*8+4];
            *(float4*)&fb[0] = *(float4*)&cW[kk][tx*8];
            *(float4*)&fb[4] = *(float4*)&cW[kk][tx*8+4];
            #pragma unroll
            for (int i = 0; i < 8; i++)
                #pragma unroll
                for (int j = 0; j < 8; j++)
                    acc[i][j] += fa[i] * fb[j];
        }

        if (has_next) {
            nA[lkg+0][lrow] = av.x; nA[lkg+1][lrow] = av.y;
            nA[lkg+2][lrow] = av.z; nA[lkg+3][lrow] = av.w;
            nW[lkg+0][lrow] = wv.x; nW[lkg+1][lrow] = wv.y;
            nW[lkg+2][lrow] = wv.z; nW[lkg+3][lrow] = wv.w;
            __syncthreads();
            float (*t)[132];
            t = cA; cA = nA; nA = t;
            t = cW; cW = nW; nW = t;
        }
    }

    // ----- epilogue -----
    #pragma unroll
    for (int i = 0; i < 8; i++) {
        const int m = m0 + ty * 8 + i;
        if (MODE == 0) {
            const int b = m >> 11;        // m / L_
            const int l = m & 2047;
            #pragma unroll
            for (int jv = 0; jv < 8; jv += 4) {
                const int n     = n0 + tx * 8 + jv;
                const int which = n >> 10;          // 0=q 1=k 2=v
                const int rem   = n & 1023;
                const int h     = rem >> 6;
                const int hd    = rem & 63;
                float4 o;
                o.x = acc[i][jv+0]; o.y = acc[i][jv+1];
                o.z = acc[i][jv+2]; o.w = acc[i][jv+3];
                if (which == 0) {
                    o.x += bias0[rem+0]; o.y += bias0[rem+1];
                    o.z += bias0[rem+2]; o.w += bias0[rem+3];
                } else if (which == 2) {
                    o.x += bias1[rem+0]; o.y += bias1[rem+1];
                    o.z += bias1[rem+2]; o.w += bias1[rem+3];
                }
                float* dst = (which == 0) ? g_q : (which == 1) ? g_k : g_v;
                *(float4*)&dst[(((size_t)(b * H_ + h)) * L_ + l) * HD_ + hd] = o;
            }
        } else {
            #pragma unroll
            for (int jv = 0; jv < 8; jv += 4) {
                const int n = n0 + tx * 8 + jv;
                float4 o;
                o.x = acc[i][jv+0] + bias0[n+0];
                o.y = acc[i][jv+1] + bias0[n+1];
                o.z = acc[i][jv+2] + bias0[n+2];
                o.w = acc[i][jv+3] + bias0[n+3];
                *(float4*)&out[(size_t)m * C_ + n] = o;
            }
        }
    }
}

// ---------------------------------------------------------------------------
// L2-normalize q (×exp(min(scale_mul,log100))) and k. One warp per 64-elem row.
// ---------------------------------------------------------------------------
__global__ __launch_bounds__(256) void norm_kernel(const float* __restrict__ scale_mul)
{
    const int row  = blockIdx.x * 8 + (threadIdx.x >> 5);   // 0 .. 2*B*H*L-1
    const int lane = threadIdx.x & 31;
    const int NROW = B_ * H_ * L_;                          // 65536
    float* base = (row < NROW) ? (g_q + (size_t)row * HD_)
                               : (g_k + (size_t)(row - NROW) * HD_);
    float2 v = *(float2*)(base + lane * 2);
    float ss = v.x * v.x + v.y * v.y;
    #pragma unroll
    for (int off = 16; off; off >>= 1)
        ss += __shfl_xor_sync(0xffffffffu, ss, off, 32);
    float s = rsqrtf(ss);
    if (row < NROW) {
        const int h = (row >> 11) & 15;
        s *= __expf(fminf(scale_mul[h], 4.6051702f));  // log(100)
    }
    v.x *= s; v.y *= s;
    *(float2*)(base + lane * 2) = v;
}

// ---------------------------------------------------------------------------
// Fused flash attention. Block = (q-tile of 64 rows) x (one b,h).
// 256 threads as 16x16: thread(ty,tx) owns S rows 4ty+i, S cols tx+16j,
// O cols 4tx+dd. Online softmax with width-16 shuffle reductions.
// ---------------------------------------------------------------------------
__global__ __launch_bounds__(256) void attn_kernel(const float* __restrict__ bias)
{
    extern __shared__ float smem[];
    float* Qs = smem;               // [64][68]
    float* Ks = Qs + 64 * 68;       // [64][68]
    float* Vs = Ks + 64 * 68;       // [64][68]
    float* Ps = Vs + 64 * 68;       // [64][64]

    const int tid = threadIdx.x;
    const int tx  = tid & 15;
    const int ty  = tid >> 4;
    const int bh  = blockIdx.y;              // b*H + h
    const int q0  = blockIdx.x * 64;

    const float* qp    = g_q + ((size_t)bh * L_ + q0) * HD_;
    const float* kbase = g_k + (size_t)bh * L_ * HD_;
    const float* vbase = g_v + (size_t)bh * L_ * HD_;

    // load Q tile (coalesced)
    #pragma unroll
    for (int it = 0; it < 4; it++) {
        const int idx = tid + it * 256;
        const int r = idx >> 4, dg = (idx & 15) * 4;
        *(float4*)&Qs[r * 68 + dg] = *(const float4*)(qp + r * HD_ + dg);
    }

    float m_i[4], l_i[4], O[4][4];
    #pragma unroll
    for (int i = 0; i < 4; i++) {
        m_i[i] = -1e30f; l_i[i] = 0.f;
        #pragma unroll
        for (int d = 0; d < 4; d++) O[i][d] = 0.f;
    }

    for (int k0 = 0; k0 < L_; k0 += 64) {
        __syncthreads();   // protect Ks/Vs/Ps reuse from previous chunk
        #pragma unroll
        for (int it = 0; it < 4; it++) {
            const int idx = tid + it * 256;
            const int r = idx >> 4, dg = (idx & 15) * 4;
            *(float4*)&Ks[r * 68 + dg] = *(const float4*)(kbase + (size_t)(k0 + r) * HD_ + dg);
            *(float4*)&Vs[r * 68 + dg] = *(const float4*)(vbase + (size_t)(k0 + r) * HD_ + dg);
        }
        __syncthreads();

        // S = Q @ K^T  (4x4 per thread)
        float s[4][4];
        #pragma unroll
        for (int i = 0; i < 4; i++)
            #pragma unroll
            for (int j = 0; j < 4; j++) s[i][j] = 0.f;

        #pragma unroll 4
        for (int d = 0; d < 64; d += 4) {
            float qf[4][4], kf[4][4];
            #pragma unroll
            for (int i = 0; i < 4; i++)
                *(float4*)qf[i] = *(float4*)&Qs[(4 * ty + i) * 68 + d];
            #pragma unroll
            for (int j = 0; j < 4; j++)
                *(float4*)kf[j] = *(float4*)&Ks[(tx + 16 * j) * 68 + d];
            #pragma unroll
            for (int i = 0; i < 4; i++)
                #pragma unroll
                for (int j = 0; j < 4; j++) {
                    s[i][j] += qf[i][0] * kf[j][0];
                    s[i][j] += qf[i][1] * kf[j][1];
                    s[i][j] += qf[i][2] * kf[j][2];
                    s[i][j] += qf[i][3] * kf[j][3];
                }
        }

        // + bias, online softmax
        #pragma unroll
        for (int i = 0; i < 4; i++) {
            const int r = q0 + 4 * ty + i;
            const float* brow = bias + (size_t)r * L_ + k0;
            #pragma unroll
            for (int j = 0; j < 4; j++)
                s[i][j] += __ldg(&brow[tx + 16 * j]);

            float mx = fmaxf(fmaxf(s[i][0], s[i][1]), fmaxf(s[i][2], s[i][3]));
            #pragma unroll
            for (int off = 8; off; off >>= 1)
                mx = fmaxf(mx, __shfl_xor_sync(0xffffffffu, mx, off, 16));
            const float mnew  = fmaxf(m_i[i], mx);
            const float alpha = __expf(m_i[i] - mnew);
            float rs = 0.f;
            #pragma unroll
            for (int j = 0; j < 4; j++) {
                s[i][j] = __expf(s[i][j] - mnew);
                rs += s[i][j];
            }
            #pragma unroll
            for (int off = 8; off; off >>= 1)
                rs += __shfl_xor_sync(0xffffffffu, rs, off, 16);
            l_i[i] = l_i[i] * alpha + rs;
            m_i[i] = mnew;
            #pragma unroll
            for (int d = 0; d < 4; d++) O[i][d] *= alpha;
            #pragma unroll
            for (int j = 0; j < 4; j++)
                Ps[(4 * ty + i) * 64 + tx + 16 * j] = s[i][j];
        }
        __syncthreads();

        // O += P @ V
        #pragma unroll 4
        for (int c = 0; c < 64; c += 4) {
            float pf[4][4], vf[4][4];
            #pragma unroll
            for (int i = 0; i < 4; i++)
                *(float4*)pf[i] = *(float4*)&Ps[(4 * ty + i) * 64 + c];
            #pragma unroll
            for (int cc = 0; cc < 4; cc++)
                *(float4*)vf[cc] = *(float4*)&Vs[(c + cc) * 68 + 4 * tx];
            #pragma unroll
            for (int i = 0; i < 4; i++)
                #pragma unroll
                for (int cc = 0; cc < 4; cc++) {
                    O[i][0] += pf[i][cc] * vf[cc][0];
                    O[i][1] += pf[i][cc] * vf[cc][1];
                    O[i][2] += pf[i][cc] * vf[cc][2];
                    O[i][3] += pf[i][cc] * vf[cc][3];
                }
        }
    }

    // epilogue: O /= l, write to g_ao[b][l][h*64 + d]
    const int b = bh >> 4;
    const int h = bh & 15;
    #pragma unroll
    for (int i = 0; i < 4; i++) {
        const float inv = 1.f / l_i[i];
        float4 o;
        o.x = O[i][0] * inv; o.y = O[i][1] * inv;
        o.z = O[i][2] * inv; o.w = O[i][3] * inv;
        const int l = q0 + 4 * ty + i;
        *(float4*)&g_ao[((size_t)b * L_ + l) * C_ + h * 64 + 4 * tx] = o;
    }
}

// ---------------------------------------------------------------------------
extern "C" void kernel_launch(void* const* d_in, const int* in_sizes, int n_in,
                              void* d_out, int out_size)
{
    (void)in_sizes; (void)n_in; (void)out_size;
    const float* x         = (const float*)d_in[0];
    const float* attn_bias = (const float*)d_in[1];
    const float* w_qkv     = (const float*)d_in[2];
    const float* q_bias    = (const float*)d_in[3];
    const float* v_bias    = (const float*)d_in[4];
    const float* scale_mul = (const float*)d_in[5];
    const float* w_proj    = (const float*)d_in[6];
    const float* b_proj    = (const float*)d_in[7];
    float* out = (float*)d_out;

    // 1) QKV projection: [4096,1024] x [3072,1024]^T
    gemm_kernel<0><<<dim3(NQKV_/128, M_/128), 256>>>(x, w_qkv, q_bias, v_bias, nullptr);

    // 2) L2 normalize q (with per-head scale) and k
    norm_kernel<<<(2 * B_ * H_ * L_) / 8, 256>>>(scale_mul);

    // 3) fused attention
    const int smem_bytes = (3 * 64 * 68 + 64 * 64) * (int)sizeof(float);  // 68608
    static int attr_done = 0;
    // attribute set is idempotent; safe during capture (not a stream op)
    cudaFuncSetAttribute(attn_kernel, cudaFuncAttributeMaxDynamicSharedMemorySize, smem_bytes);
    (void)attr_done;
    attn_kernel<<<dim3(L_/64, B_*H_), 256, smem_bytes>>>(attn_bias);

    // 4) output projection: [4096,1024] x [1024,1024]^T + b_proj
    gemm_kernel<1><<<dim3(C_/128, M_/128), 256>>>(nullptr, w_proj, b_proj, nullptr, out);
}

// round 11
// speedup vs baseline: 2.8378x; 2.8378x over previous
#include <cuda_runtime.h>
#include <cuda_fp16.h>
#include <cstdint>
#include <math.h>

#define B_  2
#define L_  2048
#define C_  1024
#define H_  16
#define HD_ 64
#define M_  (B_*L_)      // 4096
#define BH_ (B_*H_)      // 32

// ---------------- scratch (device globals: allocation-free rule) -----------
__device__ __half g_xh [M_*C_],    g_xl [M_*C_];     // x split
__device__ __half g_wh [3*C_*C_],  g_wl [3*C_*C_];   // w_qkv split
__device__ __half g_pwh[C_*C_],    g_pwl[C_*C_];     // w_proj split
__device__ float  g_q[BH_*L_*HD_], g_k[BH_*L_*HD_], g_v[BH_*L_*HD_];
__device__ __half g_qh[BH_*L_*HD_];                  // normalized+scaled q (fp16)
__device__ __half g_kh[BH_*L_*HD_];                  // normalized k (fp16)
__device__ __half g_vth[BH_*HD_*L_], g_vtl[BH_*HD_*L_]; // V^T split [bh][hd][l]
__device__ __half g_aoh[M_*C_], g_aol[M_*C_];        // attn out split

// ---------------- asm helpers ----------------------------------------------
__device__ __forceinline__ uint32_t smem_u32(const void* p){
    uint32_t a;
    asm("{ .reg .u64 t; cvta.to.shared.u64 t, %1; cvt.u32.u64 %0, t; }" : "=r"(a) : "l"(p));
    return a;
}
#define LDSM4(r0,r1,r2,r3,addr) asm volatile( \
    "ldmatrix.sync.aligned.m8n8.x4.shared.b16 {%0,%1,%2,%3}, [%4];" \
    : "=r"(r0),"=r"(r1),"=r"(r2),"=r"(r3) : "r"(addr))

#define MMA(d, a, b0v, b1v) asm volatile( \
    "mma.sync.aligned.m16n8k16.row.col.f32.f16.f16.f32 " \
    "{%0,%1,%2,%3}, {%4,%5,%6,%7}, {%8,%9}, {%0,%1,%2,%3};" \
    : "+f"((d)[0]),"+f"((d)[1]),"+f"((d)[2]),"+f"((d)[3]) \
    : "r"((a)[0]),"r"((a)[1]),"r"((a)[2]),"r"((a)[3]), "r"(b0v),"r"(b1v))

#define CP16(dst,src) asm volatile("cp.async.cg.shared.global [%0], [%1], 16;" :: "r"(dst), "l"(src))
#define CPCOMMIT()    asm volatile("cp.async.commit_group;" ::: "memory")
#define CPWAIT0()     asm volatile("cp.async.wait_group 0;" ::: "memory")

__device__ __forceinline__ uint32_t packh2(float a, float b){
    __half2 t = __floats2half2_rn(a, b);
    return *reinterpret_cast<uint32_t*>(&t);
}
__device__ __forceinline__ void spl(float x, __half &h, __half &l){
    h = __float2half_rn(x);
    l = __float2half_rn(x - __half2float(h));
}

// ---------------- fp32 -> (hi,lo) fp16 split --------------------------------
__global__ __launch_bounds__(256) void split_sel(const float* __restrict__ s, int which, int n4){
    int i = blockIdx.x * 256 + threadIdx.x;
    if (i >= n4) return;
    __half *hp, *lp;
    if (which == 0)      { hp = g_xh;  lp = g_xl;  }
    else if (which == 1) { hp = g_wh;  lp = g_wl;  }
    else                 { hp = g_pwh; lp = g_pwl; }
    float4 v = ((const float4*)s)[i];
    __half h0,l0,h1,l1,h2,l2,h3,l3;
    spl(v.x,h0,l0); spl(v.y,h1,l1); spl(v.z,h2,l2); spl(v.w,h3,l3);
    ((__half2*)hp)[2*i]   = __halves2half2(h0,h1);
    ((__half2*)hp)[2*i+1] = __halves2half2(h2,h3);
    ((__half2*)lp)[2*i]   = __halves2half2(l0,l1);
    ((__half2*)lp)[2*i+1] = __halves2half2(l2,l3);
}

// ---------------- split-fp16 mma.sync GEMM ----------------------------------
// out[m,n] = sum_k A[m,k]*W[n,k]. Block 128x128, BK=32, 8 warps (4M x 2N),
// warp tile 32x64. 3 MMAs per position (AhBh + AhBl + AlBh). cp.async 2-stage.
template<int MODE>
__global__ __launch_bounds__(256) void gemm_mma(const float* __restrict__ bias0,
                                                const float* __restrict__ bias1,
                                                float* __restrict__ out)
{
    extern __shared__ char smem[];
    const uint32_t sb = smem_u32(smem);
    const int tid = threadIdx.x;
    const int w = tid >> 5, lane = tid & 31;
    const int wm = w & 3, wn = w >> 2;
    const int g = lane >> 2, c = lane & 3;
    const int m0 = blockIdx.y * 128, n0 = blockIdx.x * 128;

    const __half* Ah = (MODE==0) ? g_xh  : g_aoh;
    const __half* Al = (MODE==0) ? g_xl  : g_aol;
    const __half* Bh = (MODE==0) ? g_wh  : g_pwh;
    const __half* Bl = (MODE==0) ? g_wl  : g_pwl;

    const uint32_t SZ  = 10240;   // one [128][40] half tile (rows padded to 40)
    const uint32_t BUF = 4*SZ;    // 40960 per stage

    const int lr = tid >> 2;            // 0..63
    const int lc = (tid & 3) << 3;      // 0,8,16,24
    const size_t offA = (size_t)(m0 + lr) * C_ + lc;
    const size_t offB = (size_t)(n0 + lr) * C_ + lc;
    const uint32_t sdst = (uint32_t)(lr * 40 + lc) * 2;

    float acc[2][8][4];
    #pragma unroll
    for (int i=0;i<2;i++)
        #pragma unroll
        for (int j=0;j<8;j++)
            #pragma unroll
            for (int k=0;k<4;k++) acc[i][j][k]=0.f;

    // prefetch kt=0 into buf0
    #pragma unroll
    for (int i=0;i<2;i++){
        uint32_t d = sb + sdst + i*5120;               // 64 rows * 80B
        size_t sa = offA + (size_t)i*64*C_;
        size_t sw = offB + (size_t)i*64*C_;
        CP16(d + 0*SZ, Ah + sa);  CP16(d + 1*SZ, Al + sa);
        CP16(d + 2*SZ, Bh + sw);  CP16(d + 3*SZ, Bl + sw);
    }
    CPCOMMIT(); CPWAIT0(); __syncthreads();

    #pragma unroll 1
    for (int kt = 0; kt < 32; kt++) {
        if (kt < 31) {
            uint32_t bb = sb + (uint32_t)(((kt+1)&1))*BUF;
            #pragma unroll
            for (int i=0;i<2;i++){
                uint32_t d = bb + sdst + i*5120;
                size_t sa = offA + (size_t)i*64*C_ + (kt+1)*32;
                size_t sw = offB + (size_t)i*64*C_ + (kt+1)*32;
                CP16(d + 0*SZ, Ah + sa);  CP16(d + 1*SZ, Al + sa);
                CP16(d + 2*SZ, Bh + sw);  CP16(d + 3*SZ, Bl + sw);
            }
            CPCOMMIT();
        }
        const uint32_t base = sb + (uint32_t)(kt&1)*BUF;
        #pragma unroll
        for (int ks=0; ks<2; ks++){
            uint32_t afh[2][4], afl[2][4];
            #pragma unroll
            for (int mf=0; mf<2; mf++){
                uint32_t ar = (uint32_t)((wm*32 + mf*16 + (lane&15))*40 + ks*16 + (lane>>4)*8)*2;
                LDSM4(afh[mf][0],afh[mf][1],afh[mf][2],afh[mf][3], base + 0*SZ + ar);
                LDSM4(afl[mf][0],afl[mf][1],afl[mf][2],afl[mf][3], base + 1*SZ + ar);
            }
            #pragma unroll
            for (int nf2=0; nf2<4; nf2++){
                uint32_t br = (uint32_t)((wn*64 + nf2*16 + (lane&7) + ((lane>>4)<<3))*40
                                         + ks*16 + (((lane>>3)&1)<<3))*2;
                uint32_t bh0,bh1,bh2,bh3, bl0,bl1,bl2,bl3;
                LDSM4(bh0,bh1,bh2,bh3, base + 2*SZ + br);
                LDSM4(bl0,bl1,bl2,bl3, base + 3*SZ + br);
                #pragma unroll
                for (int mf=0; mf<2; mf++){
                    MMA(acc[mf][2*nf2],   afh[mf], bh0,bh1);
                    MMA(acc[mf][2*nf2],   afh[mf], bl0,bl1);
                    MMA(acc[mf][2*nf2],   afl[mf], bh0,bh1);
                    MMA(acc[mf][2*nf2+1], afh[mf], bh2,bh3);
                    MMA(acc[mf][2*nf2+1], afh[mf], bl2,bl3);
                    MMA(acc[mf][2*nf2+1], afl[mf], bh2,bh3);
                }
            }
        }
        if (kt < 31) { CPWAIT0(); __syncthreads(); }
    }

    // ---- epilogue ----
    if (MODE == 0){
        const int which = n0 >> 10;
        float* dst = (which==0) ? g_q : (which==1) ? g_k : g_v;
        const float* bsrc = (which==0) ? bias0 : (which==2) ? bias1 : nullptr;
        #pragma unroll
        for (int mf=0; mf<2; mf++)
        #pragma unroll
        for (int hh=0; hh<2; hh++){
            int m = m0 + wm*32 + mf*16 + g + hh*8;
            int b = m >> 11, l = m & (L_-1);
            #pragma unroll
            for (int nf=0; nf<8; nf++){
                int rem = (n0 & (C_-1)) + wn*64 + nf*8 + 2*c;
                int h = rem >> 6, hd = rem & 63;
                float2 o;
                o.x = acc[mf][nf][hh*2+0];
                o.y = acc[mf][nf][hh*2+1];
                if (bsrc){ o.x += bsrc[rem]; o.y += bsrc[rem+1]; }
                *(float2*)&dst[(((size_t)(b*H_+h))*L_ + l)*HD_ + hd] = o;
            }
        }
    } else {
        #pragma unroll
        for (int mf=0; mf<2; mf++)
        #pragma unroll
        for (int hh=0; hh<2; hh++){
            int m = m0 + wm*32 + mf*16 + g + hh*8;
            #pragma unroll
            for (int nf=0; nf<8; nf++){
                int n = n0 + wn*64 + nf*8 + 2*c;
                float2 o;
                o.x = acc[mf][nf][hh*2+0] + bias0[n];
                o.y = acc[mf][nf][hh*2+1] + bias0[n+1];
                *(float2*)&out[(size_t)m*C_ + n] = o;
            }
        }
    }
}

// ---------------- L2-normalize q (x scale) and k -> fp16 --------------------
__global__ __launch_bounds__(256) void norm_kernel(const float* __restrict__ scale_mul)
{
    const int row  = blockIdx.x * 8 + (threadIdx.x >> 5);
    const int lane = threadIdx.x & 31;
    const int NR   = BH_ * L_;
    const bool isq = row < NR;
    const int r2   = isq ? row : row - NR;
    const float* src = isq ? (g_q + (size_t)r2 * HD_) : (g_k + (size_t)r2 * HD_);
    float2 v = ((const float2*)src)[lane];
    float ss = v.x * v.x + v.y * v.y;
    #pragma unroll
    for (int o = 16; o; o >>= 1) ss += __shfl_xor_sync(0xffffffffu, ss, o);
    float s = rsqrtf(ss);
    if (isq) s *= __expf(fminf(scale_mul[(r2 >> 11) & 15], 4.6051702f));
    __half2* dst = (__half2*)(isq ? g_qh : g_kh);
    dst[(size_t)r2 * 32 + lane] = __floats2half2_rn(v.x * s, v.y * s);
}

// ---------------- transpose V [bh][l][hd] -> split fp16 [bh][hd][l] ---------
__global__ void vtrans_kernel()
{
    __shared__ float t[32][33];
    const int bh = blockIdx.z, l0 = blockIdx.x * 32, d0 = blockIdx.y * 32;
    const int tx = threadIdx.x, ty = threadIdx.y;
    for (int i = ty; i < 32; i += 8)
        t[i][tx] = g_v[((size_t)bh * L_ + l0 + i) * HD_ + d0 + tx];
    __syncthreads();
    for (int i = ty; i < 32; i += 8) {
        float x = t[tx][i];
        __half h, l; spl(x, h, l);
        size_t o = ((size_t)bh * HD_ + d0 + i) * L_ + l0 + tx;
        g_vth[o] = h; g_vtl[o] = l;
    }
}

// ---------------- fused FA2-style attention ---------------------------------
// CTA = 128 q rows x one bh; 8 warps, each owns a 16-row strip.
// Per 128-key chunk: S = q K^T (mma), softmax in regs (no max-sub; scores
// bounded), P converted in-register to A-frags, O += P(Vh+Vl). O and lsum
// persist across chunks. cp.async double-buffered K/V.
__device__ __forceinline__ void attn_load_chunk(uint32_t dstbase, int bh, int k0, int tid){
    #pragma unroll
    for (int i=0;i<4;i++){                     // K chunk: 128 keys x 64 hd
        int idx = i*256 + tid;
        int r = idx >> 3, cg = (idx & 7) << 3;
        CP16(dstbase + (uint32_t)(r*72 + cg)*2,
             g_kh + ((size_t)bh*L_ + k0 + r)*HD_ + cg);
    }
    #pragma unroll
    for (int i=0;i<4;i++){                     // Vt hi/lo: 64 hd x 128 l
        int idx = i*256 + tid;
        int d = idx >> 4, cg = (idx & 15) << 3;
        size_t s = ((size_t)bh*HD_ + d)*L_ + k0 + cg;
        uint32_t so = (uint32_t)(d*136 + cg)*2;
        CP16(dstbase + 18432 + so, g_vth + s);
        CP16(dstbase + 35840 + so, g_vtl + s);
    }
}

__global__ __launch_bounds__(256) void attn_mma(const float* __restrict__ bias)
{
    extern __shared__ char smem[];
    const uint32_t sb = smem_u32(smem);
    const int tid = threadIdx.x, w = tid >> 5, lane = tid & 31;
    const int g = lane >> 2, c = lane & 3;
    const int bh = blockIdx.y, q0 = blockIdx.x * 128;
    // smem: Q [128][72] @0 (18432B); chunk buf = K[128][72] + VH[64][136] + VL[64][136]
    const uint32_t CB0 = 18432, CSZ = 53248;   // 18432 + 17408 + 17408

    #pragma unroll
    for (int i=0;i<4;i++){                     // Q plain load
        int idx = i*256 + tid;
        int r = idx >> 3, cg = (idx & 7) << 3;
        uint4 v = *(const uint4*)(g_qh + ((size_t)bh*L_ + q0 + r)*HD_ + cg);
        *(uint4*)(smem + (r*72 + cg)*2) = v;
    }
    attn_load_chunk(sb + CB0, bh, 0, tid);
    CPCOMMIT(); CPWAIT0(); __syncthreads();

    uint32_t qf[4][4];
    #pragma unroll
    for (int ks=0; ks<4; ks++){
        uint32_t a = sb + (uint32_t)((w*16 + (lane&15))*72 + ks*16 + (lane>>4)*8)*2;
        LDSM4(qf[ks][0],qf[ks][1],qf[ks][2],qf[ks][3], a);
    }

    float Of[8][4];
    #pragma unroll
    for (int i=0;i<8;i++){ Of[i][0]=Of[i][1]=Of[i][2]=Of[i][3]=0.f; }
    float ls0 = 0.f, ls1 = 0.f;
    const float* bp0 = bias + (size_t)(q0 + w*16 + g) * L_;

    #pragma unroll 1
    for (int ch = 0; ch < 16; ch++){
        if (ch < 15){
            attn_load_chunk(sb + CB0 + (uint32_t)(((ch+1)&1))*CSZ, bh, (ch+1)*128, tid);
            CPCOMMIT();
        }
        const uint32_t kb = sb + CB0 + (uint32_t)(ch&1)*CSZ;

        float sacc[16][4];
        #pragma unroll
        for (int i=0;i<16;i++){ sacc[i][0]=sacc[i][1]=sacc[i][2]=sacc[i][3]=0.f; }
        #pragma unroll
        for (int ks=0; ks<4; ks++){
            #pragma unroll
            for (int nf2=0; nf2<8; nf2++){
                uint32_t a = kb + (uint32_t)((nf2*16 + (lane&7) + ((lane>>4)<<3))*72
                                             + ks*16 + (((lane>>3)&1)<<3))*2;
                uint32_t b0,b1,b2,b3;
                LDSM4(b0,b1,b2,b3, a);
                MMA(sacc[2*nf2],   qf[ks], b0,b1);
                MMA(sacc[2*nf2+1], qf[ks], b2,b3);
            }
        }
        const int k0 = ch*128;
        #pragma unroll
        for (int nf=0; nf<16; nf++){           // softmax in place (bounded scores)
            float2 bb0 = *(const float2*)(bp0 + k0 + nf*8 + 2*c);
            float2 bb1 = *(const float2*)(bp0 + 8*L_ + k0 + nf*8 + 2*c);
            sacc[nf][0] = __expf(sacc[nf][0] + bb0.x);
            sacc[nf][1] = __expf(sacc[nf][1] + bb0.y);
            sacc[nf][2] = __expf(sacc[nf][2] + bb1.x);
            sacc[nf][3] = __expf(sacc[nf][3] + bb1.y);
            ls0 += sacc[nf][0] + sacc[nf][1];
            ls1 += sacc[nf][2] + sacc[nf][3];
        }
        #pragma unroll
        for (int ks=0; ks<8; ks++){            // O += P (Vh + Vl)
            uint32_t pa[4];
            pa[0] = packh2(sacc[2*ks][0],   sacc[2*ks][1]);
            pa[1] = packh2(sacc[2*ks][2],   sacc[2*ks][3]);
            pa[2] = packh2(sacc[2*ks+1][0], sacc[2*ks+1][1]);
            pa[3] = packh2(sacc[2*ks+1][2], sacc[2*ks+1][3]);
            #pragma unroll
            for (int nf2=0; nf2<4; nf2++){
                uint32_t ro = (uint32_t)((nf2*16 + (lane&7) + ((lane>>4)<<3))*136
                                         + ks*16 + (((lane>>3)&1)<<3))*2;
                uint32_t h0,h1,h2,h3, l0,l1,l2,l3;
                LDSM4(h0,h1,h2,h3, kb + 18432 + ro);
                LDSM4(l0,l1,l2,l3, kb + 35840 + ro);
                MMA(Of[2*nf2],   pa, h0,h1);
                MMA(Of[2*nf2],   pa, l0,l1);
                MMA(Of[2*nf2+1], pa, h2,h3);
                MMA(Of[2*nf2+1], pa, l2,l3);
            }
        }
        if (ch < 15){ CPWAIT0(); __syncthreads(); }
    }

    ls0 += __shfl_xor_sync(0xffffffffu, ls0, 1);
    ls0 += __shfl_xor_sync(0xffffffffu, ls0, 2);
    ls1 += __shfl_xor_sync(0xffffffffu, ls1, 1);
    ls1 += __shfl_xor_sync(0xffffffffu, ls1, 2);
    const float i0 = 1.f/ls0, i1 = 1.f/ls1;
    const int b = bh >> 4, h = bh & 15;
    const int lr = q0 + w*16 + g;
    #pragma unroll
    for (int nf=0; nf<8; nf++){
        int col = h*64 + nf*8 + 2*c;
        size_t o0 = ((size_t)b*L_ + lr)*C_ + col;
        size_t o1 = o0 + (size_t)8*C_;
        float v0 = Of[nf][0]*i0, v1 = Of[nf][1]*i0;
        float v2 = Of[nf][2]*i1, v3 = Of[nf][3]*i1;
        __half a0,b0h,a1,b1h,a2,b2h,a3,b3h;
        spl(v0,a0,b0h); spl(v1,a1,b1h); spl(v2,a2,b2h); spl(v3,a3,b3h);
        *(__half2*)&g_aoh[o0] = __halves2half2(a0,a1);
        *(__half2*)&g_aoh[o1] = __halves2half2(a2,a3);
        *(__half2*)&g_aol[o0] = __halves2half2(b0h,b1h);
        *(__half2*)&g_aol[o1] = __halves2half2(b2h,b3h);
    }
}

// ---------------------------------------------------------------------------
extern "C" void kernel_launch(void* const* d_in, const int* in_sizes, int n_in,
                              void* d_out, int out_size)
{
    (void)in_sizes; (void)n_in; (void)out_size;
    const float* x         = (const float*)d_in[0];
    const float* attn_bias = (const float*)d_in[1];
    const float* w_qkv     = (const float*)d_in[2];
    const float* q_bias    = (const float*)d_in[3];
    const float* v_bias    = (const float*)d_in[4];
    const float* scale_mul = (const float*)d_in[5];
    const float* w_proj    = (const float*)d_in[6];
    const float* b_proj    = (const float*)d_in[7];
    float* out = (float*)d_out;

    const int GEMM_SMEM = 81920;
    const int ATT_SMEM  = 124928;
    cudaFuncSetAttribute(gemm_mma<0>, cudaFuncAttributeMaxDynamicSharedMemorySize, GEMM_SMEM);
    cudaFuncSetAttribute(gemm_mma<1>, cudaFuncAttributeMaxDynamicSharedMemorySize, GEMM_SMEM);
    cudaFuncSetAttribute(attn_mma,    cudaFuncAttributeMaxDynamicSharedMemorySize, ATT_SMEM);

    // 0) split inputs to (hi,lo) fp16
    split_sel<<<(M_*C_/4 + 255)/256, 256>>>(x, 0, M_*C_/4);
    split_sel<<<(3*C_*C_/4 + 255)/256, 256>>>(w_qkv, 1, 3*C_*C_/4);
    split_sel<<<(C_*C_/4 + 255)/256, 256>>>(w_proj, 2, C_*C_/4);

    // 1) QKV projection (split fp16 mma)
    gemm_mma<0><<<dim3(3*C_/128, M_/128), 256, GEMM_SMEM>>>(q_bias, v_bias, nullptr);

    // 2) L2 normalize q,k -> fp16
    norm_kernel<<<(2 * BH_ * L_) / 8, 256>>>(scale_mul);

    // 3) transpose + split V
    vtrans_kernel<<<dim3(L_/32, HD_/32, BH_), dim3(32, 8)>>>();

    // 4) fused attention
    attn_mma<<<dim3(L_/128, BH_), 256, ATT_SMEM>>>(attn_bias);

    // 5) output projection (split fp16 mma)
    gemm_mma<1><<<dim3(C_/128, M_/128), 256, GEMM_SMEM>>>(b_proj, nullptr, out);
}

// round 12
// speedup vs baseline: 3.3024x; 1.1637x over previous
#include <cuda_runtime.h>
#include <cuda_fp16.h>
#include <cstdint>
#include <math.h>

#define B_  2
#define L_  2048
#define C_  1024
#define H_  16
#define HD_ 64
#define M_  (B_*L_)      // 4096
#define BH_ (B_*H_)      // 32

// ---------------- scratch (device globals: allocation-free rule) -----------
__device__ __half g_xh [M_*C_],    g_xl [M_*C_];     // x split
__device__ __half g_wh [3*C_*C_],  g_wl [3*C_*C_];   // w_qkv split
__device__ __half g_pwh[C_*C_],    g_pwl[C_*C_];     // w_proj split
__device__ float  g_v[BH_*L_*HD_];
__device__ __half g_qh[BH_*L_*HD_];                  // normalized+scaled q (fp16)
__device__ __half g_kh[BH_*L_*HD_];                  // normalized k (fp16)
__device__ __half g_vth[BH_*HD_*L_], g_vtl[BH_*HD_*L_]; // V^T split [bh][hd][l]
__device__ __half g_aoh[M_*C_], g_aol[M_*C_];        // attn out split

// ---------------- asm helpers ----------------------------------------------
__device__ __forceinline__ uint32_t smem_u32(const void* p){
    uint32_t a;
    asm("{ .reg .u64 t; cvta.to.shared.u64 t, %1; cvt.u32.u64 %0, t; }" : "=r"(a) : "l"(p));
    return a;
}
#define LDSM4(r0,r1,r2,r3,addr) asm volatile( \
    "ldmatrix.sync.aligned.m8n8.x4.shared.b16 {%0,%1,%2,%3}, [%4];" \
    : "=r"(r0),"=r"(r1),"=r"(r2),"=r"(r3) : "r"(addr))

#define MMA(d, a, b0v, b1v) asm volatile( \
    "mma.sync.aligned.m16n8k16.row.col.f32.f16.f16.f32 " \
    "{%0,%1,%2,%3}, {%4,%5,%6,%7}, {%8,%9}, {%0,%1,%2,%3};" \
    : "+f"((d)[0]),"+f"((d)[1]),"+f"((d)[2]),"+f"((d)[3]) \
    : "r"((a)[0]),"r"((a)[1]),"r"((a)[2]),"r"((a)[3]), "r"(b0v),"r"(b1v))

#define CP16(dst,src) asm volatile("cp.async.cg.shared.global [%0], [%1], 16;" :: "r"(dst), "l"(src))
#define CPCOMMIT()    asm volatile("cp.async.commit_group;" ::: "memory")
#define CPWAIT0()     asm volatile("cp.async.wait_group 0;" ::: "memory")

__device__ __forceinline__ uint32_t packh2(float a, float b){
    __half2 t = __floats2half2_rn(a, b);
    return *reinterpret_cast<uint32_t*>(&t);
}
__device__ __forceinline__ void spl(float x, __half &h, __half &l){
    h = __float2half_rn(x);
    l = __float2half_rn(x - __half2float(h));
}

// ---------------- fp32 -> (hi,lo) fp16 split --------------------------------
__global__ __launch_bounds__(256) void split_sel(const float* __restrict__ s, int which, int n4){
    int i = blockIdx.x * 256 + threadIdx.x;
    if (i >= n4) return;
    __half *hp, *lp;
    if (which == 0)      { hp = g_xh;  lp = g_xl;  }
    else if (which == 1) { hp = g_wh;  lp = g_wl;  }
    else                 { hp = g_pwh; lp = g_pwl; }
    float4 v = ((const float4*)s)[i];
    __half h0,l0,h1,l1,h2,l2,h3,l3;
    spl(v.x,h0,l0); spl(v.y,h1,l1); spl(v.z,h2,l2); spl(v.w,h3,l3);
    ((__half2*)hp)[2*i]   = __halves2half2(h0,h1);
    ((__half2*)hp)[2*i+1] = __halves2half2(h2,h3);
    ((__half2*)lp)[2*i]   = __halves2half2(l0,l1);
    ((__half2*)lp)[2*i+1] = __halves2half2(l2,l3);
}

// ---------------- split-fp16 mma.sync GEMM ----------------------------------
// out[m,n] = sum_k A[m,k]*W[n,k]. Block 128x128, BK=32, 8 warps (4M x 2N),
// warp tile 32x64, 3 MMAs/pos. cp.async 2-stage. 2 CTAs/SM (reg cap 128).
// MODE 0: qkv epilogue — q/k rows L2-normalized in-place (quad shuffle) and
//         written fp16 to g_qh/g_kh; v written fp32 (+v_bias) to g_v.
// MODE 1: proj epilogue — +b_proj, write d_out.
template<int MODE>
__global__ __launch_bounds__(256, 2) void gemm_mma(const float* __restrict__ bias0,
                                                   const float* __restrict__ bias1,
                                                   const float* __restrict__ scale_mul,
                                                   float* __restrict__ out)
{
    extern __shared__ char smem[];
    const uint32_t sb = smem_u32(smem);
    const int tid = threadIdx.x;
    const int w = tid >> 5, lane = tid & 31;
    const int wm = w & 3, wn = w >> 2;
    const int g = lane >> 2, c = lane & 3;
    const int m0 = blockIdx.y * 128, n0 = blockIdx.x * 128;

    const __half* Ah = (MODE==0) ? g_xh  : g_aoh;
    const __half* Al = (MODE==0) ? g_xl  : g_aol;
    const __half* Bh = (MODE==0) ? g_wh  : g_pwh;
    const __half* Bl = (MODE==0) ? g_wl  : g_pwl;

    const uint32_t SZ  = 10240;   // one [128][40] half tile
    const uint32_t BUF = 4*SZ;    // 40960 per stage

    const int lr = tid >> 2;
    const int lc = (tid & 3) << 3;
    const size_t offA = (size_t)(m0 + lr) * C_ + lc;
    const size_t offB = (size_t)(n0 + lr) * C_ + lc;
    const uint32_t sdst = (uint32_t)(lr * 40 + lc) * 2;

    float acc[2][8][4];
    #pragma unroll
    for (int i=0;i<2;i++)
        #pragma unroll
        for (int j=0;j<8;j++)
            #pragma unroll
            for (int k=0;k<4;k++) acc[i][j][k]=0.f;

    #pragma unroll
    for (int i=0;i<2;i++){
        uint32_t d = sb + sdst + i*5120;
        size_t sa = offA + (size_t)i*64*C_;
        size_t sw = offB + (size_t)i*64*C_;
        CP16(d + 0*SZ, Ah + sa);  CP16(d + 1*SZ, Al + sa);
        CP16(d + 2*SZ, Bh + sw);  CP16(d + 3*SZ, Bl + sw);
    }
    CPCOMMIT(); CPWAIT0(); __syncthreads();

    #pragma unroll 1
    for (int kt = 0; kt < 32; kt++) {
        if (kt < 31) {
            uint32_t bb = sb + (uint32_t)(((kt+1)&1))*BUF;
            #pragma unroll
            for (int i=0;i<2;i++){
                uint32_t d = bb + sdst + i*5120;
                size_t sa = offA + (size_t)i*64*C_ + (kt+1)*32;
                size_t sw = offB + (size_t)i*64*C_ + (kt+1)*32;
                CP16(d + 0*SZ, Ah + sa);  CP16(d + 1*SZ, Al + sa);
                CP16(d + 2*SZ, Bh + sw);  CP16(d + 3*SZ, Bl + sw);
            }
            CPCOMMIT();
        }
        const uint32_t base = sb + (uint32_t)(kt&1)*BUF;
        #pragma unroll
        for (int ks=0; ks<2; ks++){
            uint32_t afh[2][4], afl[2][4];
            #pragma unroll
            for (int mf=0; mf<2; mf++){
                uint32_t ar = (uint32_t)((wm*32 + mf*16 + (lane&15))*40 + ks*16 + (lane>>4)*8)*2;
                LDSM4(afh[mf][0],afh[mf][1],afh[mf][2],afh[mf][3], base + 0*SZ + ar);
                LDSM4(afl[mf][0],afl[mf][1],afl[mf][2],afl[mf][3], base + 1*SZ + ar);
            }
            #pragma unroll
            for (int nf2=0; nf2<4; nf2++){
                uint32_t br = (uint32_t)((wn*64 + nf2*16 + (lane&7) + ((lane>>4)<<3))*40
                                         + ks*16 + (((lane>>3)&1)<<3))*2;
                uint32_t bh0,bh1,bh2,bh3, bl0,bl1,bl2,bl3;
                LDSM4(bh0,bh1,bh2,bh3, base + 2*SZ + br);
                LDSM4(bl0,bl1,bl2,bl3, base + 3*SZ + br);
                #pragma unroll
                for (int mf=0; mf<2; mf++){
                    MMA(acc[mf][2*nf2],   afh[mf], bh0,bh1);
                    MMA(acc[mf][2*nf2],   afh[mf], bl0,bl1);
                    MMA(acc[mf][2*nf2],   afl[mf], bh0,bh1);
                    MMA(acc[mf][2*nf2+1], afh[mf], bh2,bh3);
                    MMA(acc[mf][2*nf2+1], afh[mf], bl2,bl3);
                    MMA(acc[mf][2*nf2+1], afl[mf], bh2,bh3);
                }
            }
        }
        if (kt < 31) { CPWAIT0(); __syncthreads(); }
    }

    // ---- epilogue ----
    if (MODE == 0){
        const int which = n0 >> 10;                 // 0=q 1=k 2=v
        const int h = ((n0 & (C_-1)) + wn*64) >> 6; // head (warp-uniform)
        if (which == 2){
            #pragma unroll
            for (int mf=0; mf<2; mf++)
            #pragma unroll
            for (int hh=0; hh<2; hh++){
                int m = m0 + wm*32 + mf*16 + g + hh*8;
                int b = m >> 11, l = m & (L_-1);
                size_t rowb = (((size_t)(b*H_+h))*L_ + l)*HD_;
                #pragma unroll
                for (int nf=0; nf<8; nf++){
                    int hd = nf*8 + 2*c;
                    int rem = (n0 & (C_-1)) + wn*64 + hd;
                    float2 o;
                    o.x = acc[mf][nf][hh*2+0] + bias1[rem];
                    o.y = acc[mf][nf][hh*2+1] + bias1[rem+1];
                    *(float2*)&g_v[rowb + hd] = o;
                }
            }
        } else {
            __half* dst = (which == 0) ? g_qh : g_kh;
            float smul = 1.f;
            if (which == 0) smul = __expf(fminf(scale_mul[h], 4.6051702f));
            #pragma unroll
            for (int mf=0; mf<2; mf++)
            #pragma unroll
            for (int hh=0; hh<2; hh++){
                int m = m0 + wm*32 + mf*16 + g + hh*8;
                int b = m >> 11, l = m & (L_-1);
                float vals[16];
                float ss = 0.f;
                #pragma unroll
                for (int nf=0; nf<8; nf++){
                    int rem = (n0 & (C_-1)) + wn*64 + nf*8 + 2*c;
                    float vx = acc[mf][nf][hh*2+0];
                    float vy = acc[mf][nf][hh*2+1];
                    if (which == 0){ vx += bias0[rem]; vy += bias0[rem+1]; }
                    vals[2*nf] = vx; vals[2*nf+1] = vy;
                    ss += vx*vx + vy*vy;
                }
                ss += __shfl_xor_sync(0xffffffffu, ss, 1);
                ss += __shfl_xor_sync(0xffffffffu, ss, 2);
                float s = rsqrtf(ss) * smul;
                size_t rowb = (((size_t)(b*H_+h))*L_ + l)*HD_;
                #pragma unroll
                for (int nf=0; nf<8; nf++)
                    *(__half2*)&dst[rowb + nf*8 + 2*c] =
                        __floats2half2_rn(vals[2*nf]*s, vals[2*nf+1]*s);
            }
        }
    } else {
        #pragma unroll
        for (int mf=0; mf<2; mf++)
        #pragma unroll
        for (int hh=0; hh<2; hh++){
            int m = m0 + wm*32 + mf*16 + g + hh*8;
            #pragma unroll
            for (int nf=0; nf<8; nf++){
                int n = n0 + wn*64 + nf*8 + 2*c;
                float2 o;
                o.x = acc[mf][nf][hh*2+0] + bias0[n];
                o.y = acc[mf][nf][hh*2+1] + bias0[n+1];
                *(float2*)&out[(size_t)m*C_ + n] = o;
            }
        }
    }
}

// ---------------- transpose V [bh][l][hd] -> split fp16 [bh][hd][l] ---------
__global__ void vtrans_kernel()
{
    __shared__ float t[32][33];
    const int bh = blockIdx.z, l0 = blockIdx.x * 32, d0 = blockIdx.y * 32;
    const int tx = threadIdx.x, ty = threadIdx.y;
    for (int i = ty; i < 32; i += 8)
        t[i][tx] = g_v[((size_t)bh * L_ + l0 + i) * HD_ + d0 + tx];
    __syncthreads();
    for (int i = ty; i < 32; i += 8) {
        float x = t[tx][i];
        __half h, l; spl(x, h, l);
        size_t o = ((size_t)bh * HD_ + d0 + i) * L_ + l0 + tx;
        g_vth[o] = h; g_vtl[o] = l;
    }
}

// ---------------- fused FA2-style attention ---------------------------------
// CTA = 128 q rows x one bh; 8 warps x 16-row strips; 64-key chunks (32 iters),
// cp.async double-buffered; 2 CTAs/SM. Bounded scores -> softmax w/o max-sub;
// O and lsum persist in registers across all chunks.
__device__ __forceinline__ void attn_load_chunk(uint32_t dstbase, int bh, int k0, int tid){
    #pragma unroll
    for (int i=0;i<2;i++){                     // K chunk: 64 keys x 64 hd
        int idx = i*256 + tid;
        int r = idx >> 3, cg = (idx & 7) << 3;
        CP16(dstbase + (uint32_t)(r*72 + cg)*2,
             g_kh + ((size_t)bh*L_ + k0 + r)*HD_ + cg);
    }
    #pragma unroll
    for (int i=0;i<2;i++){                     // Vt hi/lo: 64 hd x 64 keys
        int idx = i*256 + tid;
        int d = idx >> 3, cg = (idx & 7) << 3;
        size_t s = ((size_t)bh*HD_ + d)*L_ + k0 + cg;
        uint32_t so = (uint32_t)(d*72 + cg)*2;
        CP16(dstbase +  9216 + so, g_vth + s);
        CP16(dstbase + 18432 + so, g_vtl + s);
    }
}

__global__ __launch_bounds__(256, 2) void attn_mma(const float* __restrict__ bias)
{
    extern __shared__ char smem[];
    const uint32_t sb = smem_u32(smem);
    const int tid = threadIdx.x, w = tid >> 5, lane = tid & 31;
    const int g = lane >> 2, c = lane & 3;
    const int bh = blockIdx.y, q0 = blockIdx.x * 128;
    // smem: Q[128][72] @0 (18432B); chunk = K[64][72] + VH[64][72] + VL[64][72]
    const uint32_t CB0 = 18432, CSZ = 27648;

    #pragma unroll
    for (int i=0;i<4;i++){                     // Q plain load
        int idx = i*256 + tid;
        int r = idx >> 3, cg = (idx & 7) << 3;
        uint4 v = *(const uint4*)(g_qh + ((size_t)bh*L_ + q0 + r)*HD_ + cg);
        *(uint4*)(smem + (r*72 + cg)*2) = v;
    }
    attn_load_chunk(sb + CB0, bh, 0, tid);
    CPCOMMIT(); CPWAIT0(); __syncthreads();

    uint32_t qf[4][4];
    #pragma unroll
    for (int ks=0; ks<4; ks++){
        uint32_t a = sb + (uint32_t)((w*16 + (lane&15))*72 + ks*16 + (lane>>4)*8)*2;
        LDSM4(qf[ks][0],qf[ks][1],qf[ks][2],qf[ks][3], a);
    }

    float Of[8][4];
    #pragma unroll
    for (int i=0;i<8;i++){ Of[i][0]=Of[i][1]=Of[i][2]=Of[i][3]=0.f; }
    float ls0 = 0.f, ls1 = 0.f;
    const float* bp0 = bias + (size_t)(q0 + w*16 + g) * L_;

    #pragma unroll 1
    for (int ch = 0; ch < 32; ch++){
        if (ch < 31){
            attn_load_chunk(sb + CB0 + (uint32_t)(((ch+1)&1))*CSZ, bh, (ch+1)*64, tid);
            CPCOMMIT();
        }
        const uint32_t kb = sb + CB0 + (uint32_t)(ch&1)*CSZ;

        float sacc[8][4];
        #pragma unroll
        for (int i=0;i<8;i++){ sacc[i][0]=sacc[i][1]=sacc[i][2]=sacc[i][3]=0.f; }
        #pragma unroll
        for (int ks=0; ks<4; ks++){
            #pragma unroll
            for (int nf2=0; nf2<4; nf2++){
                uint32_t a = kb + (uint32_t)((nf2*16 + (lane&7) + ((lane>>4)<<3))*72
                                             + ks*16 + (((lane>>3)&1)<<3))*2;
                uint32_t b0,b1,b2,b3;
                LDSM4(b0,b1,b2,b3, a);
                MMA(sacc[2*nf2],   qf[ks], b0,b1);
                MMA(sacc[2*nf2+1], qf[ks], b2,b3);
            }
        }
        const int k0 = ch*64;
        #pragma unroll
        for (int nf=0; nf<8; nf++){            // softmax (bounded scores)
            float2 bb0 = *(const float2*)(bp0 + k0 + nf*8 + 2*c);
            float2 bb1 = *(const float2*)(bp0 + 8*L_ + k0 + nf*8 + 2*c);
            sacc[nf][0] = __expf(sacc[nf][0] + bb0.x);
            sacc[nf][1] = __expf(sacc[nf][1] + bb0.y);
            sacc[nf][2] = __expf(sacc[nf][2] + bb1.x);
            sacc[nf][3] = __expf(sacc[nf][3] + bb1.y);
            ls0 += sacc[nf][0] + sacc[nf][1];
            ls1 += sacc[nf][2] + sacc[nf][3];
        }
        #pragma unroll
        for (int ks=0; ks<4; ks++){            // O += P (Vh + Vl)
            uint32_t pa[4];
            pa[0] = packh2(sacc[2*ks][0],   sacc[2*ks][1]);
            pa[1] = packh2(sacc[2*ks][2],   sacc[2*ks][3]);
            pa[2] = packh2(sacc[2*ks+1][0], sacc[2*ks+1][1]);
            pa[3] = packh2(sacc[2*ks+1][2], sacc[2*ks+1][3]);
            #pragma unroll
            for (int nf2=0; nf2<4; nf2++){
                uint32_t ro = (uint32_t)((nf2*16 + (lane&7) + ((lane>>4)<<3))*72
                                         + ks*16 + (((lane>>3)&1)<<3))*2;
                uint32_t h0,h1,h2,h3, l0,l1,l2,l3;
                LDSM4(h0,h1,h2,h3, kb +  9216 + ro);
                LDSM4(l0,l1,l2,l3, kb + 18432 + ro);
                MMA(Of[2*nf2],   pa, h0,h1);
                MMA(Of[2*nf2],   pa, l0,l1);
                MMA(Of[2*nf2+1], pa, h2,h3);
                MMA(Of[2*nf2+1], pa, l2,l3);
            }
        }
        if (ch < 31){ CPWAIT0(); __syncthreads(); }
    }

    ls0 += __shfl_xor_sync(0xffffffffu, ls0, 1);
    ls0 += __shfl_xor_sync(0xffffffffu, ls0, 2);
    ls1 += __shfl_xor_sync(0xffffffffu, ls1, 1);
    ls1 += __shfl_xor_sync(0xffffffffu, ls1, 2);
    const float i0 = 1.f/ls0, i1 = 1.f/ls1;
    const int b = bh >> 4, h = bh & 15;
    const int lr = q0 + w*16 + g;
    #pragma unroll
    for (int nf=0; nf<8; nf++){
        int col = h*64 + nf*8 + 2*c;
        size_t o0 = ((size_t)b*L_ + lr)*C_ + col;
        size_t o1 = o0 + (size_t)8*C_;
        float v0 = Of[nf][0]*i0, v1 = Of[nf][1]*i0;
        float v2 = Of[nf][2]*i1, v3 = Of[nf][3]*i1;
        __half a0,b0h,a1,b1h,a2,b2h,a3,b3h;
        spl(v0,a0,b0h); spl(v1,a1,b1h); spl(v2,a2,b2h); spl(v3,a3,b3h);
        *(__half2*)&g_aoh[o0] = __halves2half2(a0,a1);
        *(__half2*)&g_aoh[o1] = __halves2half2(a2,a3);
        *(__half2*)&g_aol[o0] = __halves2half2(b0h,b1h);
        *(__half2*)&g_aol[o1] = __halves2half2(b2h,b3h);
    }
}

// ---------------------------------------------------------------------------
extern "C" void kernel_launch(void* const* d_in, const int* in_sizes, int n_in,
                              void* d_out, int out_size)
{
    (void)in_sizes; (void)n_in; (void)out_size;
    const float* x         = (const float*)d_in[0];
    const float* attn_bias = (const float*)d_in[1];
    const float* w_qkv     = (const float*)d_in[2];
    const float* q_bias    = (const float*)d_in[3];
    const float* v_bias    = (const float*)d_in[4];
    const float* scale_mul = (const float*)d_in[5];
    const float* w_proj    = (const float*)d_in[6];
    const float* b_proj    = (const float*)d_in[7];
    float* out = (float*)d_out;

    const int GEMM_SMEM = 81920;
    const int ATT_SMEM  = 73728;
    cudaFuncSetAttribute(gemm_mma<0>, cudaFuncAttributeMaxDynamicSharedMemorySize, GEMM_SMEM);
    cudaFuncSetAttribute(gemm_mma<1>, cudaFuncAttributeMaxDynamicSharedMemorySize, GEMM_SMEM);
    cudaFuncSetAttribute(attn_mma,    cudaFuncAttributeMaxDynamicSharedMemorySize, ATT_SMEM);

    // 0) split inputs to (hi,lo) fp16
    split_sel<<<(M_*C_/4 + 255)/256, 256>>>(x, 0, M_*C_/4);
    split_sel<<<(3*C_*C_/4 + 255)/256, 256>>>(w_qkv, 1, 3*C_*C_/4);
    split_sel<<<(C_*C_/4 + 255)/256, 256>>>(w_proj, 2, C_*C_/4);

    // 1) QKV projection + fused q/k L2-norm (split fp16 mma)
    gemm_mma<0><<<dim3(3*C_/128, M_/128), 256, GEMM_SMEM>>>(q_bias, v_bias, scale_mul, nullptr);

    // 2) transpose + split V
    vtrans_kernel<<<dim3(L_/32, HD_/32, BH_), dim3(32, 8)>>>();

    // 3) fused attention
    attn_mma<<<dim3(L_/128, BH_), 256, ATT_SMEM>>>(attn_bias);

    // 4) output projection (split fp16 mma)
    gemm_mma<1><<<dim3(C_/128, M_/128), 256, GEMM_SMEM>>>(b_proj, nullptr, nullptr, out);
}

// round 13
// speedup vs baseline: 5.6949x; 1.7245x over previous
#include <cuda_runtime.h>
#include <cuda_fp16.h>
#include <cstdint>
#include <math.h>

#define B_  2
#define L_  2048
#define C_  1024
#define H_  16
#define HD_ 64
#define M_  (B_*L_)      // 4096
#define BH_ (B_*H_)      // 32

// ---------------- scratch (device globals: allocation-free rule) -----------
__device__ __half g_xh [M_*C_];                      // x fp16
__device__ __half g_wh [3*C_*C_];                    // w_qkv fp16
__device__ __half g_pwh[C_*C_];                      // w_proj fp16
__device__ float  g_v[BH_*L_*HD_];
__device__ __half g_qh[BH_*L_*HD_];                  // normalized+scaled q (fp16)
__device__ __half g_kh[BH_*L_*HD_];                  // normalized k (fp16)
__device__ __half g_vth[BH_*HD_*L_];                 // V^T fp16 [bh][hd][l]
__device__ __half g_aoh[M_*C_];                      // attn out fp16

// ---------------- asm helpers ----------------------------------------------
__device__ __forceinline__ uint32_t smem_u32(const void* p){
    uint32_t a;
    asm("{ .reg .u64 t; cvta.to.shared.u64 t, %1; cvt.u32.u64 %0, t; }" : "=r"(a) : "l"(p));
    return a;
}
#define LDSM4(r0,r1,r2,r3,addr) asm volatile( \
    "ldmatrix.sync.aligned.m8n8.x4.shared.b16 {%0,%1,%2,%3}, [%4];" \
    : "=r"(r0),"=r"(r1),"=r"(r2),"=r"(r3) : "r"(addr))

#define MMA(d, a, b0v, b1v) asm volatile( \
    "mma.sync.aligned.m16n8k16.row.col.f32.f16.f16.f32 " \
    "{%0,%1,%2,%3}, {%4,%5,%6,%7}, {%8,%9}, {%0,%1,%2,%3};" \
    : "+f"((d)[0]),"+f"((d)[1]),"+f"((d)[2]),"+f"((d)[3]) \
    : "r"((a)[0]),"r"((a)[1]),"r"((a)[2]),"r"((a)[3]), "r"(b0v),"r"(b1v))

#define CP16(dst,src) asm volatile("cp.async.cg.shared.global [%0], [%1], 16;" :: "r"(dst), "l"(src))
#define CPCOMMIT()    asm volatile("cp.async.commit_group;" ::: "memory")
#define CPWAIT0()     asm volatile("cp.async.wait_group 0;" ::: "memory")

__device__ __forceinline__ uint32_t packh2(float a, float b){
    __half2 t = __floats2half2_rn(a, b);
    return *reinterpret_cast<uint32_t*>(&t);
}

// ---------------- fp32 -> fp16 convert ---------------------------------------
__global__ __launch_bounds__(256) void cvt_sel(const float* __restrict__ s, int which, int n4){
    int i = blockIdx.x * 256 + threadIdx.x;
    if (i >= n4) return;
    __half* hp = (which == 0) ? g_xh : (which == 1) ? g_wh : g_pwh;
    float4 v = ((const float4*)s)[i];
    ((__half2*)hp)[2*i]   = __floats2half2_rn(v.x, v.y);
    ((__half2*)hp)[2*i+1] = __floats2half2_rn(v.z, v.w);
}

// ---------------- fp16 mma.sync GEMM -----------------------------------------
// out[m,n] = sum_k A[m,k]*W[n,k]. Block 128x128, BK=32, 8 warps (4M x 2N),
// warp tile 32x64, 1 MMA/pos. cp.async 2-stage. 2 CTAs/SM.
// MODE 0: qkv epilogue — q/k rows L2-normalized (quad shuffle) -> fp16
//         g_qh/g_kh; v written fp32 (+v_bias) to g_v.
// MODE 1: proj epilogue — +b_proj, write d_out.
template<int MODE>
__global__ __launch_bounds__(256, 2) void gemm_mma(const float* __restrict__ bias0,
                                                   const float* __restrict__ bias1,
                                                   const float* __restrict__ scale_mul,
                                                   float* __restrict__ out)
{
    extern __shared__ char smem[];
    const uint32_t sb = smem_u32(smem);
    const int tid = threadIdx.x;
    const int w = tid >> 5, lane = tid & 31;
    const int wm = w & 3, wn = w >> 2;
    const int g = lane >> 2, c = lane & 3;
    const int m0 = blockIdx.y * 128, n0 = blockIdx.x * 128;

    const __half* Ah = (MODE==0) ? g_xh : g_aoh;
    const __half* Bh = (MODE==0) ? g_wh : g_pwh;

    const uint32_t SZ  = 10240;   // one [128][40] half tile
    const uint32_t BUF = 2*SZ;    // 20480 per stage

    const int lr = tid >> 2;
    const int lc = (tid & 3) << 3;
    const size_t offA = (size_t)(m0 + lr) * C_ + lc;
    const size_t offB = (size_t)(n0 + lr) * C_ + lc;
    const uint32_t sdst = (uint32_t)(lr * 40 + lc) * 2;

    float acc[2][8][4];
    #pragma unroll
    for (int i=0;i<2;i++)
        #pragma unroll
        for (int j=0;j<8;j++)
            #pragma unroll
            for (int k=0;k<4;k++) acc[i][j][k]=0.f;

    #pragma unroll
    for (int i=0;i<2;i++){
        uint32_t d = sb + sdst + i*5120;
        CP16(d + 0*SZ, Ah + offA + (size_t)i*64*C_);
        CP16(d + 1*SZ, Bh + offB + (size_t)i*64*C_);
    }
    CPCOMMIT(); CPWAIT0(); __syncthreads();

    #pragma unroll 1
    for (int kt = 0; kt < 32; kt++) {
        if (kt < 31) {
            uint32_t bb = sb + (uint32_t)(((kt+1)&1))*BUF;
            #pragma unroll
            for (int i=0;i<2;i++){
                uint32_t d = bb + sdst + i*5120;
                CP16(d + 0*SZ, Ah + offA + (size_t)i*64*C_ + (kt+1)*32);
                CP16(d + 1*SZ, Bh + offB + (size_t)i*64*C_ + (kt+1)*32);
            }
            CPCOMMIT();
        }
        const uint32_t base = sb + (uint32_t)(kt&1)*BUF;
        #pragma unroll
        for (int ks=0; ks<2; ks++){
            uint32_t afh[2][4];
            #pragma unroll
            for (int mf=0; mf<2; mf++){
                uint32_t ar = (uint32_t)((wm*32 + mf*16 + (lane&15))*40 + ks*16 + (lane>>4)*8)*2;
                LDSM4(afh[mf][0],afh[mf][1],afh[mf][2],afh[mf][3], base + 0*SZ + ar);
            }
            #pragma unroll
            for (int nf2=0; nf2<4; nf2++){
                uint32_t br = (uint32_t)((wn*64 + nf2*16 + (lane&7) + ((lane>>4)<<3))*40
                                         + ks*16 + (((lane>>3)&1)<<3))*2;
                uint32_t bh0,bh1,bh2,bh3;
                LDSM4(bh0,bh1,bh2,bh3, base + 1*SZ + br);
                #pragma unroll
                for (int mf=0; mf<2; mf++){
                    MMA(acc[mf][2*nf2],   afh[mf], bh0,bh1);
                    MMA(acc[mf][2*nf2+1], afh[mf], bh2,bh3);
                }
            }
        }
        if (kt < 31) { CPWAIT0(); __syncthreads(); }
    }

    // ---- epilogue ----
    if (MODE == 0){
        const int which = n0 >> 10;                 // 0=q 1=k 2=v
        const int h = ((n0 & (C_-1)) + wn*64) >> 6; // head (warp-uniform)
        if (which == 2){
            #pragma unroll
            for (int mf=0; mf<2; mf++)
            #pragma unroll
            for (int hh=0; hh<2; hh++){
                int m = m0 + wm*32 + mf*16 + g + hh*8;
                int b = m >> 11, l = m & (L_-1);
                size_t rowb = (((size_t)(b*H_+h))*L_ + l)*HD_;
                #pragma unroll
                for (int nf=0; nf<8; nf++){
                    int hd = nf*8 + 2*c;
                    int rem = (n0 & (C_-1)) + wn*64 + hd;
                    float2 o;
                    o.x = acc[mf][nf][hh*2+0] + bias1[rem];
                    o.y = acc[mf][nf][hh*2+1] + bias1[rem+1];
                    *(float2*)&g_v[rowb + hd] = o;
                }
            }
        } else {
            __half* dst = (which == 0) ? g_qh : g_kh;
            float smul = 1.f;
            if (which == 0) smul = __expf(fminf(scale_mul[h], 4.6051702f));
            #pragma unroll
            for (int mf=0; mf<2; mf++)
            #pragma unroll
            for (int hh=0; hh<2; hh++){
                int m = m0 + wm*32 + mf*16 + g + hh*8;
                int b = m >> 11, l = m & (L_-1);
                float vals[16];
                float ss = 0.f;
                #pragma unroll
                for (int nf=0; nf<8; nf++){
                    int rem = (n0 & (C_-1)) + wn*64 + nf*8 + 2*c;
                    float vx = acc[mf][nf][hh*2+0];
                    float vy = acc[mf][nf][hh*2+1];
                    if (which == 0){ vx += bias0[rem]; vy += bias0[rem+1]; }
                    vals[2*nf] = vx; vals[2*nf+1] = vy;
                    ss += vx*vx + vy*vy;
                }
                ss += __shfl_xor_sync(0xffffffffu, ss, 1);
                ss += __shfl_xor_sync(0xffffffffu, ss, 2);
                float s = rsqrtf(ss) * smul;
                size_t rowb = (((size_t)(b*H_+h))*L_ + l)*HD_;
                #pragma unroll
                for (int nf=0; nf<8; nf++)
                    *(__half2*)&dst[rowb + nf*8 + 2*c] =
                        __floats2half2_rn(vals[2*nf]*s, vals[2*nf+1]*s);
            }
        }
    } else {
        #pragma unroll
        for (int mf=0; mf<2; mf++)
        #pragma unroll
        for (int hh=0; hh<2; hh++){
            int m = m0 + wm*32 + mf*16 + g + hh*8;
            #pragma unroll
            for (int nf=0; nf<8; nf++){
                int n = n0 + wn*64 + nf*8 + 2*c;
                float2 o;
                o.x = acc[mf][nf][hh*2+0] + bias0[n];
                o.y = acc[mf][nf][hh*2+1] + bias0[n+1];
                *(float2*)&out[(size_t)m*C_ + n] = o;
            }
        }
    }
}

// ---------------- transpose V [bh][l][hd] -> fp16 [bh][hd][l] ----------------
__global__ void vtrans_kernel()
{
    __shared__ float t[32][33];
    const int bh = blockIdx.z, l0 = blockIdx.x * 32, d0 = blockIdx.y * 32;
    const int tx = threadIdx.x, ty = threadIdx.y;
    for (int i = ty; i < 32; i += 8)
        t[i][tx] = g_v[((size_t)bh * L_ + l0 + i) * HD_ + d0 + tx];
    __syncthreads();
    for (int i = ty; i < 32; i += 8)
        g_vth[((size_t)bh * HD_ + d0 + i) * L_ + l0 + tx] = __float2half_rn(t[tx][i]);
}

// ---------------- fused FA2-style attention ----------------------------------
// CTA = 128 q rows x one bh; 8 warps x 16-row strips; 64-key chunks (32 iters),
// cp.async double-buffered; 2 CTAs/SM. Bounded scores -> softmax w/o max-sub;
// O and lsum persist in registers across all chunks.
__device__ __forceinline__ void attn_load_chunk(uint32_t dstbase, int bh, int k0, int tid){
    #pragma unroll
    for (int i=0;i<2;i++){                     // K chunk: 64 keys x 64 hd
        int idx = i*256 + tid;
        int r = idx >> 3, cg = (idx & 7) << 3;
        CP16(dstbase + (uint32_t)(r*72 + cg)*2,
             g_kh + ((size_t)bh*L_ + k0 + r)*HD_ + cg);
    }
    #pragma unroll
    for (int i=0;i<2;i++){                     // Vt: 64 hd x 64 keys
        int idx = i*256 + tid;
        int d = idx >> 3, cg = (idx & 7) << 3;
        CP16(dstbase + 9216 + (uint32_t)(d*72 + cg)*2,
             g_vth + ((size_t)bh*HD_ + d)*L_ + k0 + cg);
    }
}

__global__ __launch_bounds__(256, 2) void attn_mma(const float* __restrict__ bias)
{
    extern __shared__ char smem[];
    const uint32_t sb = smem_u32(smem);
    const int tid = threadIdx.x, w = tid >> 5, lane = tid & 31;
    const int g = lane >> 2, c = lane & 3;
    const int bh = blockIdx.y, q0 = blockIdx.x * 128;
    // smem: Q[128][72] @0 (18432B); chunk = K[64][72] + VH[64][72] = 18432B
    const uint32_t CB0 = 18432, CSZ = 18432;

    #pragma unroll
    for (int i=0;i<4;i++){                     // Q plain load
        int idx = i*256 + tid;
        int r = idx >> 3, cg = (idx & 7) << 3;
        uint4 v = *(const uint4*)(g_qh + ((size_t)bh*L_ + q0 + r)*HD_ + cg);
        *(uint4*)(smem + (r*72 + cg)*2) = v;
    }
    attn_load_chunk(sb + CB0, bh, 0, tid);
    CPCOMMIT(); CPWAIT0(); __syncthreads();

    uint32_t qf[4][4];
    #pragma unroll
    for (int ks=0; ks<4; ks++){
        uint32_t a = sb + (uint32_t)((w*16 + (lane&15))*72 + ks*16 + (lane>>4)*8)*2;
        LDSM4(qf[ks][0],qf[ks][1],qf[ks][2],qf[ks][3], a);
    }

    float Of[8][4];
    #pragma unroll
    for (int i=0;i<8;i++){ Of[i][0]=Of[i][1]=Of[i][2]=Of[i][3]=0.f; }
    float ls0 = 0.f, ls1 = 0.f;
    const float* bp0 = bias + (size_t)(q0 + w*16 + g) * L_;

    #pragma unroll 1
    for (int ch = 0; ch < 32; ch++){
        if (ch < 31){
            attn_load_chunk(sb + CB0 + (uint32_t)(((ch+1)&1))*CSZ, bh, (ch+1)*64, tid);
            CPCOMMIT();
        }
        const uint32_t kb = sb + CB0 + (uint32_t)(ch&1)*CSZ;

        float sacc[8][4];
        #pragma unroll
        for (int i=0;i<8;i++){ sacc[i][0]=sacc[i][1]=sacc[i][2]=sacc[i][3]=0.f; }
        #pragma unroll
        for (int ks=0; ks<4; ks++){
            #pragma unroll
            for (int nf2=0; nf2<4; nf2++){
                uint32_t a = kb + (uint32_t)((nf2*16 + (lane&7) + ((lane>>4)<<3))*72
                                             + ks*16 + (((lane>>3)&1)<<3))*2;
                uint32_t b0,b1,b2,b3;
                LDSM4(b0,b1,b2,b3, a);
                MMA(sacc[2*nf2],   qf[ks], b0,b1);
                MMA(sacc[2*nf2+1], qf[ks], b2,b3);
            }
        }
        const int k0 = ch*64;
        #pragma unroll
        for (int nf=0; nf<8; nf++){            // softmax (bounded scores)
            float2 bb0 = *(const float2*)(bp0 + k0 + nf*8 + 2*c);
            float2 bb1 = *(const float2*)(bp0 + 8*L_ + k0 + nf*8 + 2*c);
            sacc[nf][0] = __expf(sacc[nf][0] + bb0.x);
            sacc[nf][1] = __expf(sacc[nf][1] + bb0.y);
            sacc[nf][2] = __expf(sacc[nf][2] + bb1.x);
            sacc[nf][3] = __expf(sacc[nf][3] + bb1.y);
            ls0 += sacc[nf][0] + sacc[nf][1];
            ls1 += sacc[nf][2] + sacc[nf][3];
        }
        #pragma unroll
        for (int ks=0; ks<4; ks++){            // O += P V
            uint32_t pa[4];
            pa[0] = packh2(sacc[2*ks][0],   sacc[2*ks][1]);
            pa[1] = packh2(sacc[2*ks][2],   sacc[2*ks][3]);
            pa[2] = packh2(sacc[2*ks+1][0], sacc[2*ks+1][1]);
            pa[3] = packh2(sacc[2*ks+1][2], sacc[2*ks+1][3]);
            #pragma unroll
            for (int nf2=0; nf2<4; nf2++){
                uint32_t ro = (uint32_t)((nf2*16 + (lane&7) + ((lane>>4)<<3))*72
                                         + ks*16 + (((lane>>3)&1)<<3))*2;
                uint32_t h0,h1,h2,h3;
                LDSM4(h0,h1,h2,h3, kb + 9216 + ro);
                MMA(Of[2*nf2],   pa, h0,h1);
                MMA(Of[2*nf2+1], pa, h2,h3);
            }
        }
        if (ch < 31){ CPWAIT0(); __syncthreads(); }
    }

    ls0 += __shfl_xor_sync(0xffffffffu, ls0, 1);
    ls0 += __shfl_xor_sync(0xffffffffu, ls0, 2);
    ls1 += __shfl_xor_sync(0xffffffffu, ls1, 1);
    ls1 += __shfl_xor_sync(0xffffffffu, ls1, 2);
    const float i0 = 1.f/ls0, i1 = 1.f/ls1;
    const int b = bh >> 4, h = bh & 15;
    const int lr = q0 + w*16 + g;
    #pragma unroll
    for (int nf=0; nf<8; nf++){
        int col = h*64 + nf*8 + 2*c;
        size_t o0 = ((size_t)b*L_ + lr)*C_ + col;
        size_t o1 = o0 + (size_t)8*C_;
        *(__half2*)&g_aoh[o0] = __floats2half2_rn(Of[nf][0]*i0, Of[nf][1]*i0);
        *(__half2*)&g_aoh[o1] = __floats2half2_rn(Of[nf][2]*i1, Of[nf][3]*i1);
    }
}

// ---------------------------------------------------------------------------
extern "C" void kernel_launch(void* const* d_in, const int* in_sizes, int n_in,
                              void* d_out, int out_size)
{
    (void)in_sizes; (void)n_in; (void)out_size;
    const float* x         = (const float*)d_in[0];
    const float* attn_bias = (const float*)d_in[1];
    const float* w_qkv     = (const float*)d_in[2];
    const float* q_bias    = (const float*)d_in[3];
    const float* v_bias    = (const float*)d_in[4];
    const float* scale_mul = (const float*)d_in[5];
    const float* w_proj    = (const float*)d_in[6];
    const float* b_proj    = (const float*)d_in[7];
    float* out = (float*)d_out;

    const int GEMM_SMEM = 40960;
    const int ATT_SMEM  = 55296;
    cudaFuncSetAttribute(gemm_mma<0>, cudaFuncAttributeMaxDynamicSharedMemorySize, GEMM_SMEM);
    cudaFuncSetAttribute(gemm_mma<1>, cudaFuncAttributeMaxDynamicSharedMemorySize, GEMM_SMEM);
    cudaFuncSetAttribute(attn_mma,    cudaFuncAttributeMaxDynamicSharedMemorySize, ATT_SMEM);

    // 0) convert inputs to fp16
    cvt_sel<<<(M_*C_/4 + 255)/256, 256>>>(x, 0, M_*C_/4);
    cvt_sel<<<(3*C_*C_/4 + 255)/256, 256>>>(w_qkv, 1, 3*C_*C_/4);
    cvt_sel<<<(C_*C_/4 + 255)/256, 256>>>(w_proj, 2, C_*C_/4);

    // 1) QKV projection + fused q/k L2-norm
    gemm_mma<0><<<dim3(3*C_/128, M_/128), 256, GEMM_SMEM>>>(q_bias, v_bias, scale_mul, nullptr);

    // 2) transpose V -> fp16
    vtrans_kernel<<<dim3(L_/32, HD_/32, BH_), dim3(32, 8)>>>();

    // 3) fused attention
    attn_mma<<<dim3(L_/128, BH_), 256, ATT_SMEM>>>(attn_bias);

    // 4) output projection
    gemm_mma<1><<<dim3(C_/128, M_/128), 256, GEMM_SMEM>>>(b_proj, nullptr, nullptr, out);
}